// round 7
// baseline (speedup 1.0000x reference)
#include <cuda_runtime.h>

// Problem constants (fixed by the reference)
#define NN        64
#define INV_DX    63.0f                 // 1/DX, DX = 1/(64-1)
#define DXC       (1.0f/63.0f)
#define E_OUT_C   80.0f                 // E_IN = 1
#define FOUR_PI_F 12.566370614359172f
#define EPSF      1.1920928955078125e-07f
#define EPSF2     (EPSF*EPSF)
#define TPB       512
#define WPB       16                    // warps per block
#define WPP       2                     // points per warp
#define PPB       (WPB*WPP)             // 32 points per block

__device__ float    g_accum = 0.0f;
__device__ unsigned g_count = 0;

template<int NQC>
__global__ __launch_bounds__(TPB)
void boundary_loss_fused(const float* __restrict__ outf,    // (2,1,64,64,64)
                         const float* __restrict__ q,      // (NQ)
                         const float* __restrict__ xq,     // (NQ,3)
                         const int*   __restrict__ xi,
                         const int*   __restrict__ yi,
                         const int*   __restrict__ zi,
                         const float* __restrict__ normals,// (NB,3)
                         float* __restrict__ outp,
                         int nb, int nq_rt, unsigned total_warps)
{
    const int nq = (NQC > 0) ? NQC : nq_rt;
    const int KITER = (NQC > 0) ? (NQC + 31) / 32 : 0;

    int tid  = threadIdx.x;
    int wid  = tid >> 5;
    int lane = tid & 31;

    int gw = blockIdx.x * WPB + wid;    // global warp id
    int i0 = gw * WPP;                  // two boundary points per warp
    int i1 = i0 + 1;
    bool a0 = (i0 < nb);
    bool a1 = (i1 < nb);

    // ---- point descriptors (warp-uniform broadcast loads), issued first ----
    int   x0=1, y0=1, z0=1, x1=1, y1=1, z1=1;
    float nx0=0.f, ny0=0.f, nz0=0.f, nx1=0.f, ny1=0.f, nz1=0.f;
    if (a0) {
        x0 = __ldg(xi+i0); y0 = __ldg(yi+i0); z0 = __ldg(zi+i0);
        nx0 = __ldg(normals+3*i0); ny0 = __ldg(normals+3*i0+1); nz0 = __ldg(normals+3*i0+2);
    }
    if (a1) {
        x1 = __ldg(xi+i1); y1 = __ldg(yi+i1); z1 = __ldg(zi+i1);
        nx1 = __ldg(normals+3*i1); ny1 = __ldg(normals+3*i1+1); nz1 = __ldg(normals+3*i1+2);
    }

    // ---- per-lane charge loads, direct from global (no smem, no barrier) ----
    float qj[8], cx[8], cy[8], cz[8];
    #pragma unroll
    for (int k = 0; k < ((NQC > 0) ? KITER : 0); k++) {
        int j = lane + 32 * k;
        if (j < NQC) {
            qj[k] = __ldg(q + j);
            cx[k] = __ldg(xq + 3*j);
            cy[k] = __ldg(xq + 3*j + 1);
            cz[k] = __ldg(xq + 3*j + 2);
        } else {                         // inert charge: q=0, far away
            qj[k] = 0.0f; cx[k] = 1.0e9f; cy[k] = 1.0e9f; cz[k] = 1.0e9f;
        }
    }

    // ---- stencil loads (broadcast), issued while charges are in flight ----
    float c0a=0,c0b=0,lfa=0,lfb=0,rta=0,rtb=0,bla=0,blb=0,aba=0,abb=0,bka=0,bkb=0,fra=0,frb=0;
    float d0a=0,d0b=0,lga=0,lgb=0,rua=0,rub=0,bma=0,bmb=0,aca=0,acb=0,bja=0,bjb=0,fsa=0,fsb=0;
    const float* ob0 = outf;
    const float* ob1 = outf + (long)NN * NN * NN;
    if (a0) {
        long b0 = ((long)x0 * NN + y0) * NN + z0;
        c0a = __ldg(ob0+b0);       c0b = __ldg(ob1+b0);
        lfa = __ldg(ob0+b0-NN*NN); lfb = __ldg(ob1+b0-NN*NN);
        rta = __ldg(ob0+b0+NN*NN); rtb = __ldg(ob1+b0+NN*NN);
        bla = __ldg(ob0+b0-NN);    blb = __ldg(ob1+b0-NN);
        aba = __ldg(ob0+b0+NN);    abb = __ldg(ob1+b0+NN);
        bka = __ldg(ob0+b0-1);     bkb = __ldg(ob1+b0-1);
        fra = __ldg(ob0+b0+1);     frb = __ldg(ob1+b0+1);
    }
    if (a1) {
        long b1 = ((long)x1 * NN + y1) * NN + z1;
        d0a = __ldg(ob0+b1);       d0b = __ldg(ob1+b1);
        lga = __ldg(ob0+b1-NN*NN); lgb = __ldg(ob1+b1-NN*NN);
        rua = __ldg(ob0+b1+NN*NN); rub = __ldg(ob1+b1+NN*NN);
        bma = __ldg(ob0+b1-NN);    bmb = __ldg(ob1+b1-NN);
        aca = __ldg(ob0+b1+NN);    acb = __ldg(ob1+b1+NN);
        bja = __ldg(ob0+b1-1);     bjb = __ldg(ob1+b1-1);
        fsa = __ldg(ob0+b1+1);     fsb = __ldg(ob1+b1+1);
    }

    float px0 = x0 * DXC, py0 = y0 * DXC, pz0 = z0 * DXC;
    float px1 = x1 * DXC, py1 = y1 * DXC, pz1 = z1 * DXC;

    // ---- charge accumulation: two independent chains (ILP vs MUFU latency) ----
    float gs0 = 0.f, gn0 = 0.f, gs1 = 0.f, gn1 = 0.f;
    #pragma unroll
    for (int k = 0; k < ((NQC > 0) ? KITER : 0); k++) {
        {
            float dx = px0 - cx[k], dy = py0 - cy[k], dz = pz0 - cz[k];
            float r2 = fmaf(dx, dx, fmaf(dy, dy, dz * dz));
            r2 = fmaxf(r2, EPSF2);
            float rinv = rsqrtf(r2);
            float qr   = qj[k] * rinv;
            gs0 += qr;
            float c = qr * rinv * rinv;
            float dot = fmaf(dx, nx0, fmaf(dy, ny0, dz * nz0));
            gn0 = fmaf(-c, dot, gn0);
        }
        {
            float dx = px1 - cx[k], dy = py1 - cy[k], dz = pz1 - cz[k];
            float r2 = fmaf(dx, dx, fmaf(dy, dy, dz * dz));
            r2 = fmaxf(r2, EPSF2);
            float rinv = rsqrtf(r2);
            float qr   = qj[k] * rinv;
            gs1 += qr;
            float c = qr * rinv * rinv;
            float dot = fmaf(dx, nx1, fmaf(dy, ny1, dz * nz1));
            gn1 = fmaf(-c, dot, gn1);
        }
    }
    // runtime-nq fallback path
    if (NQC == 0) {
        for (int j = lane; j < nq; j += 32) {
            float qv = __ldg(q + j);
            float xv = __ldg(xq + 3*j), yv = __ldg(xq + 3*j + 1), zv = __ldg(xq + 3*j + 2);
            float dx = px0 - xv, dy = py0 - yv, dz = pz0 - zv;
            float r2 = fmaxf(fmaf(dx, dx, fmaf(dy, dy, dz * dz)), EPSF2);
            float rinv = rsqrtf(r2);
            float qr = qv * rinv; gs0 += qr;
            float c = qr * rinv * rinv;
            gn0 = fmaf(-c, fmaf(dx, nx0, fmaf(dy, ny0, dz * nz0)), gn0);
            dx = px1 - xv; dy = py1 - yv; dz = pz1 - zv;
            r2 = fmaxf(fmaf(dx, dx, fmaf(dy, dy, dz * dz)), EPSF2);
            rinv = rsqrtf(r2);
            qr = qv * rinv; gs1 += qr;
            c = qr * rinv * rinv;
            gn1 = fmaf(-c, fmaf(dx, nx1, fmaf(dy, ny1, dz * nz1)), gn1);
        }
    }

    // ---- warp butterfly reduction: 4 values, chains interleaved ----
    #pragma unroll
    for (int s = 16; s > 0; s >>= 1) {
        gs0 += __shfl_xor_sync(0xffffffffu, gs0, s);
        gs1 += __shfl_xor_sync(0xffffffffu, gs1, s);
        gn0 += __shfl_xor_sync(0xffffffffu, gn0, s);
        gn1 += __shfl_xor_sync(0xffffffffu, gn1, s);
    }

    const float inv4pi = 1.0f / FOUR_PI_F;
    float acc = 0.0f;

    if (a0) {
        float g = gs0 * inv4pi, gcnd = gn0 * inv4pi;
        float gxin  = (nx0 > 0.0f) ? (c0a - lfa) : (rta - c0a);
        float gxout = (nx0 > 0.0f) ? (rta - c0a) : (c0a - lfa);
        float gyin  = (ny0 > 0.0f) ? (c0a - bla) : (aba - c0a);
        float gyout = (ny0 > 0.0f) ? (aba - c0a) : (c0a - bla);
        float gzin  = (nz0 > 0.0f) ? (c0a - bka) : (fra - c0a);
        float gzout = (nz0 > 0.0f) ? (fra - c0a) : (c0a - bka);
        float ndin  = (gxin *nx0 + gyin *ny0 + gzin *nz0) * INV_DX;
        float ndout = (gxout*nx0 + gyout*ny0 + gzout*nz0) * INV_DX;
        float tA = (ndin + gcnd) - E_OUT_C * ndout;
        gxin  = (nx0 > 0.0f) ? (c0b - lfb) : (rtb - c0b);
        gxout = (nx0 > 0.0f) ? (rtb - c0b) : (c0b - lfb);
        gyin  = (ny0 > 0.0f) ? (c0b - blb) : (abb - c0b);
        gyout = (ny0 > 0.0f) ? (abb - c0b) : (c0b - blb);
        gzin  = (nz0 > 0.0f) ? (c0b - bkb) : (frb - c0b);
        gzout = (nz0 > 0.0f) ? (frb - c0b) : (c0b - bkb);
        ndin  = (gxin *nx0 + gyin *ny0 + gzin *nz0) * INV_DX;
        ndout = (gxout*nx0 + gyout*ny0 + gzout*nz0) * INV_DX;
        float tB = (ndin + gcnd) - E_OUT_C * ndout;
        acc += g * g + 0.5f * (tA * tA + tB * tB);
    }
    if (a1) {
        float g = gs1 * inv4pi, gcnd = gn1 * inv4pi;
        float gxin  = (nx1 > 0.0f) ? (d0a - lga) : (rua - d0a);
        float gxout = (nx1 > 0.0f) ? (rua - d0a) : (d0a - lga);
        float gyin  = (ny1 > 0.0f) ? (d0a - bma) : (aca - d0a);
        float gyout = (ny1 > 0.0f) ? (aca - d0a) : (d0a - bma);
        float gzin  = (nz1 > 0.0f) ? (d0a - bja) : (fsa - d0a);
        float gzout = (nz1 > 0.0f) ? (fsa - d0a) : (d0a - bja);
        float ndin  = (gxin *nx1 + gyin *ny1 + gzin *nz1) * INV_DX;
        float ndout = (gxout*nx1 + gyout*ny1 + gzout*nz1) * INV_DX;
        float tA = (ndin + gcnd) - E_OUT_C * ndout;
        gxin  = (nx1 > 0.0f) ? (d0b - lgb) : (rub - d0b);
        gxout = (nx1 > 0.0f) ? (rub - d0b) : (d0b - lgb);
        gyin  = (ny1 > 0.0f) ? (d0b - bmb) : (acb - d0b);
        gyout = (ny1 > 0.0f) ? (acb - d0b) : (d0b - bmb);
        gzin  = (nz1 > 0.0f) ? (d0b - bjb) : (fsb - d0b);
        gzout = (nz1 > 0.0f) ? (fsb - d0b) : (d0b - bjb);
        ndin  = (gxin *nx1 + gyin *ny1 + gzin *nz1) * INV_DX;
        ndout = (gxout*nx1 + gyout*ny1 + gzout*nz1) * INV_DX;
        float tB = (ndin + gcnd) - E_OUT_C * ndout;
        acc += g * g + 0.5f * (tA * tA + tB * tB);
    }

    // ---- per-warp atomic, no block barrier at all ----
    if (lane == 0) {
        atomicAdd(&g_accum, acc);
        __threadfence();
        unsigned old = atomicAdd(&g_count, 1u);
        if (old == total_warps - 1u) {        // last warp: finalize + reset
            float total = *(volatile float*)&g_accum;
            outp[0] = total / (float)nb;
            g_accum = 0.0f;
            __threadfence();
            g_count = 0;
        }
    }
}

extern "C" void kernel_launch(void* const* d_in, const int* in_sizes, int n_in,
                              void* d_out, int out_size)
{
    // metadata order: output, q, xq, points, x_idx, y_idx, z_idx, normals
    const float* outf    = (const float*)d_in[0];
    const float* q       = (const float*)d_in[1];
    const float* xq      = (const float*)d_in[2];
    const int*   xi      = (const int*)  d_in[4];
    const int*   yi      = (const int*)  d_in[5];
    const int*   zi      = (const int*)  d_in[6];
    const float* normals = (const float*)d_in[7];

    int nq = in_sizes[1];
    int nb = in_sizes[4];

    int blocks = (nb + PPB - 1) / PPB;
    unsigned total_warps = (unsigned)blocks * WPB;

    if (nq == 200) {
        boundary_loss_fused<200><<<blocks, TPB>>>(outf, q, xq, xi, yi, zi, normals,
                                                  (float*)d_out, nb, nq, total_warps);
    } else {
        boundary_loss_fused<0><<<blocks, TPB>>>(outf, q, xq, xi, yi, zi, normals,
                                                (float*)d_out, nb, nq, total_warps);
    }
}

// round 11
// speedup vs baseline: 1.4154x; 1.4154x over previous
#include <cuda_runtime.h>
#include <cstdint>

// Problem constants (fixed by the reference)
#define NN        64
#define INV_DX    63.0f
#define DXC       (1.0f/63.0f)
#define E_OUT_C   80.0f
#define FOUR_PI_F 12.566370614359172f
#define EPSF      1.1920928955078125e-07f
#define EPSF2     (EPSF*EPSF)
#define TPB       512
#define WPB       16                    // warps per block
#define WPP       2                     // points per warp (packed f32x2)
#define PPB       (WPB*WPP)             // 32 points per block
#define MAXQ      512

__device__ float    g_accum = 0.0f;
__device__ unsigned g_count = 0;

// ---- packed f32x2 helpers (FFMA2 path, sm_100+) ----
#define MUL2(d,a,b)    asm("mul.rn.f32x2 %0,%1,%2;"    : "=l"(d) : "l"(a), "l"(b))
#define ADD2(d,a,b)    asm("add.rn.f32x2 %0,%1,%2;"    : "=l"(d) : "l"(a), "l"(b))
#define FMA2(d,a,b,c)  asm("fma.rn.f32x2 %0,%1,%2,%3;" : "=l"(d) : "l"(a), "l"(b), "l"(c))
#define PK2(d,lo,hi)   asm("mov.b64 %0,{%1,%2};"       : "=l"(d) : "f"(lo), "f"(hi))
#define UPK2(lo,hi,s)  asm("mov.b64 {%0,%1},%2;"       : "=f"(lo), "=f"(hi) : "l"(s))

template<int NQC>   // NQC > 0: compile-time charge count; 0: runtime nq
__global__ __launch_bounds__(TPB)
void boundary_loss_fused(const float* __restrict__ outf,    // (2,1,64,64,64)
                         const float* __restrict__ q,      // (NQ)
                         const float* __restrict__ xq,     // (NQ,3)
                         const int*   __restrict__ xi,
                         const int*   __restrict__ yi,
                         const int*   __restrict__ zi,
                         const float* __restrict__ normals,// (NB,3)
                         float* __restrict__ outp,
                         int nb, int nq_rt)
{
    const int nq = (NQC > 0) ? NQC : nq_rt;

    __shared__ float4 s4[MAXQ];         // {-x, -y, -z, q} per charge
    __shared__ float  warp_acc[WPB];

    int tid  = threadIdx.x;
    int wid  = tid >> 5;
    int lane = tid & 31;

    // stage charges (negated coords so the loop uses add.f32x2, no sub needed)
    for (int j = tid; j < nq && j < MAXQ; j += TPB) {
        float4 v;
        v.x = -xq[3*j + 0];
        v.y = -xq[3*j + 1];
        v.z = -xq[3*j + 2];
        v.w =  q[j];
        s4[j] = v;
    }

    int gw = blockIdx.x * WPB + wid;
    int i0 = gw * WPP;
    int i1 = i0 + 1;
    bool a0 = (i0 < nb);
    bool a1 = (i1 < nb);
    int i1c = a1 ? i1 : (a0 ? i0 : 0);  // clamp for safe loads
    int i0c = a0 ? i0 : 0;

    // ---- point descriptors, issued before the barrier ----
    int   x0 = xi[i0c], y0 = yi[i0c], z0 = zi[i0c];
    int   x1 = xi[i1c], y1 = yi[i1c], z1 = zi[i1c];
    float nx0 = normals[3*i0c], ny0 = normals[3*i0c+1], nz0 = normals[3*i0c+2];
    float nx1 = normals[3*i1c], ny1 = normals[3*i1c+1], nz1 = normals[3*i1c+2];

    // ---- stencil loads (broadcast), also pre-barrier ----
    const float* ob0 = outf;
    const float* ob1 = outf + (long)NN * NN * NN;
    long b0 = ((long)x0 * NN + y0) * NN + z0;
    long b1 = ((long)x1 * NN + y1) * NN + z1;
    float c0a = ob0[b0],       c0b = ob1[b0];
    float lfa = ob0[b0-NN*NN], lfb = ob1[b0-NN*NN];
    float rta = ob0[b0+NN*NN], rtb = ob1[b0+NN*NN];
    float bla = ob0[b0-NN],    blb = ob1[b0-NN];
    float aba = ob0[b0+NN],    abb = ob1[b0+NN];
    float bka = ob0[b0-1],     bkb = ob1[b0-1];
    float fra = ob0[b0+1],     frb = ob1[b0+1];
    float d0a = ob0[b1],       d0b = ob1[b1];
    float lga = ob0[b1-NN*NN], lgb = ob1[b1-NN*NN];
    float rua = ob0[b1+NN*NN], rub = ob1[b1+NN*NN];
    float bma = ob0[b1-NN],    bmb = ob1[b1-NN];
    float aca = ob0[b1+NN],    acb = ob1[b1+NN];
    float bja = ob0[b1-1],     bjb = ob1[b1-1];
    float fsa = ob0[b1+1],     fsb = ob1[b1+1];

    __syncthreads();

    // packed per-pair constants
    uint64_t PX, PY, PZ, NX2, NY2, NZ2, GS, GN;
    PK2(PX, x0 * DXC, x1 * DXC);
    PK2(PY, y0 * DXC, y1 * DXC);
    PK2(PZ, z0 * DXC, z1 * DXC);
    PK2(NX2, nx0, nx1);
    PK2(NY2, ny0, ny1);
    PK2(NZ2, nz0, nz1);
    PK2(GS, 0.0f, 0.0f);
    PK2(GN, 0.0f, 0.0f);

    // ---- packed charge loop: 2 points per f32x2 op ----
    const int KIT = (NQC > 0) ? (NQC + 31) / 32 : 0;
    #pragma unroll
    for (int k = 0; k < KIT; k++) {
        int j = lane + 32 * k;
        float4 v;
        if (j < NQC) v = s4[j];
        else { v.x = 1.0e9f; v.y = 1.0e9f; v.z = 1.0e9f; v.w = 0.0f; }  // inert

        uint64_t NCX, NCY, NCZ, QQ;
        PK2(NCX, v.x, v.x);
        PK2(NCY, v.y, v.y);
        PK2(NCZ, v.z, v.z);
        PK2(QQ,  v.w, v.w);

        uint64_t DX, DY, DZ, R2, RINV, QR, C, DOT;
        ADD2(DX, PX, NCX);
        ADD2(DY, PY, NCY);
        ADD2(DZ, PZ, NCZ);
        MUL2(R2, DZ, DZ);
        FMA2(R2, DY, DY, R2);
        FMA2(R2, DX, DX, R2);

        float ra, rb;
        UPK2(ra, rb, R2);
        ra = fmaxf(ra, EPSF2);          // r==0 EPS semantics (grad term has dr=0)
        rb = fmaxf(rb, EPSF2);
        float ria = rsqrtf(ra);
        float rib = rsqrtf(rb);
        PK2(RINV, ria, rib);

        MUL2(QR, QQ, RINV);             // q / r
        ADD2(GS, GS, QR);
        MUL2(C, QR, RINV);
        MUL2(C, C, RINV);               // q / r^3
        MUL2(DOT, DZ, NZ2);
        FMA2(DOT, DY, NY2, DOT);
        FMA2(DOT, DX, NX2, DOT);
        FMA2(GN, C, DOT, GN);           // accumulates +c*dot; negate at end
    }

    float gs0, gs1, gn0, gn1;
    UPK2(gs0, gs1, GS);
    UPK2(gn0, gn1, GN);

    // runtime-nq fallback (scalar)
    if (NQC == 0) {
        for (int j = lane; j < nq; j += 32) {
            float4 v = s4[j];
            float dx = x0*DXC + v.x, dy = y0*DXC + v.y, dz = z0*DXC + v.z;
            float r2 = fmaxf(fmaf(dx,dx,fmaf(dy,dy,dz*dz)), EPSF2);
            float ri = rsqrtf(r2);
            float qr = v.w * ri; gs0 += qr;
            gn0 = fmaf(qr*ri*ri, fmaf(dx,nx0,fmaf(dy,ny0,dz*nz0)), gn0);
            dx = x1*DXC + v.x; dy = y1*DXC + v.y; dz = z1*DXC + v.z;
            r2 = fmaxf(fmaf(dx,dx,fmaf(dy,dy,dz*dz)), EPSF2);
            ri = rsqrtf(r2);
            qr = v.w * ri; gs1 += qr;
            gn1 = fmaf(qr*ri*ri, fmaf(dx,nx1,fmaf(dy,ny1,dz*nz1)), gn1);
        }
    }

    // ---- warp butterfly reduction ----
    #pragma unroll
    for (int s = 16; s > 0; s >>= 1) {
        gs0 += __shfl_xor_sync(0xffffffffu, gs0, s);
        gs1 += __shfl_xor_sync(0xffffffffu, gs1, s);
        gn0 += __shfl_xor_sync(0xffffffffu, gn0, s);
        gn1 += __shfl_xor_sync(0xffffffffu, gn1, s);
    }

    const float inv4pi = 1.0f / FOUR_PI_F;
    float acc = 0.0f;

    if (a0) {
        float g = gs0 * inv4pi, gcnd = -gn0 * inv4pi;
        float gxin  = (nx0 > 0.0f) ? (c0a - lfa) : (rta - c0a);
        float gxout = (nx0 > 0.0f) ? (rta - c0a) : (c0a - lfa);
        float gyin  = (ny0 > 0.0f) ? (c0a - bla) : (aba - c0a);
        float gyout = (ny0 > 0.0f) ? (aba - c0a) : (c0a - bla);
        float gzin  = (nz0 > 0.0f) ? (c0a - bka) : (fra - c0a);
        float gzout = (nz0 > 0.0f) ? (fra - c0a) : (c0a - bka);
        float ndin  = (gxin *nx0 + gyin *ny0 + gzin *nz0) * INV_DX;
        float ndout = (gxout*nx0 + gyout*ny0 + gzout*nz0) * INV_DX;
        float tA = (ndin + gcnd) - E_OUT_C * ndout;
        gxin  = (nx0 > 0.0f) ? (c0b - lfb) : (rtb - c0b);
        gxout = (nx0 > 0.0f) ? (rtb - c0b) : (c0b - lfb);
        gyin  = (ny0 > 0.0f) ? (c0b - blb) : (abb - c0b);
        gyout = (ny0 > 0.0f) ? (abb - c0b) : (c0b - blb);
        gzin  = (nz0 > 0.0f) ? (c0b - bkb) : (frb - c0b);
        gzout = (nz0 > 0.0f) ? (frb - c0b) : (c0b - bkb);
        ndin  = (gxin *nx0 + gyin *ny0 + gzin *nz0) * INV_DX;
        ndout = (gxout*nx0 + gyout*ny0 + gzout*nz0) * INV_DX;
        float tB = (ndin + gcnd) - E_OUT_C * ndout;
        acc += g * g + 0.5f * (tA * tA + tB * tB);
    }
    if (a1) {
        float g = gs1 * inv4pi, gcnd = -gn1 * inv4pi;
        float gxin  = (nx1 > 0.0f) ? (d0a - lga) : (rua - d0a);
        float gxout = (nx1 > 0.0f) ? (rua - d0a) : (d0a - lga);
        float gyin  = (ny1 > 0.0f) ? (d0a - bma) : (aca - d0a);
        float gyout = (ny1 > 0.0f) ? (aca - d0a) : (d0a - bma);
        float gzin  = (nz1 > 0.0f) ? (d0a - bja) : (fsa - d0a);
        float gzout = (nz1 > 0.0f) ? (fsa - d0a) : (d0a - bja);
        float ndin  = (gxin *nx1 + gyin *ny1 + gzin *nz1) * INV_DX;
        float ndout = (gxout*nx1 + gyout*ny1 + gzout*nz1) * INV_DX;
        float tA = (ndin + gcnd) - E_OUT_C * ndout;
        gxin  = (nx1 > 0.0f) ? (d0b - lgb) : (rub - d0b);
        gxout = (nx1 > 0.0f) ? (rub - d0b) : (d0b - lgb);
        gyin  = (ny1 > 0.0f) ? (d0b - bmb) : (acb - d0b);
        gyout = (ny1 > 0.0f) ? (acb - d0b) : (d0b - bmb);
        gzin  = (nz1 > 0.0f) ? (d0b - bjb) : (fsb - d0b);
        gzout = (nz1 > 0.0f) ? (fsb - d0b) : (d0b - bjb);
        ndin  = (gxin *nx1 + gyin *ny1 + gzin *nz1) * INV_DX;
        ndout = (gxout*nx1 + gyout*ny1 + gzout*nz1) * INV_DX;
        float tB = (ndin + gcnd) - E_OUT_C * ndout;
        acc += g * g + 0.5f * (tA * tA + tB * tB);
    }

    // ---- block reduction: one value per warp ----
    if (lane == 0) warp_acc[wid] = acc;
    __syncthreads();

    if (tid == 0) {
        float bsum = 0.0f;
        #pragma unroll
        for (int w = 0; w < WPB; w++) bsum += warp_acc[w];
        atomicAdd(&g_accum, bsum);
        __threadfence();
        unsigned old = atomicAdd(&g_count, 1u);
        if (old == gridDim.x - 1) {           // last block: finalize + reset
            float total = *(volatile float*)&g_accum;
            outp[0] = total / (float)nb;
            g_accum = 0.0f;
            __threadfence();
            g_count = 0;
        }
    }
}

extern "C" void kernel_launch(void* const* d_in, const int* in_sizes, int n_in,
                              void* d_out, int out_size)
{
    // metadata order: output, q, xq, points, x_idx, y_idx, z_idx, normals
    const float* outf    = (const float*)d_in[0];
    const float* q       = (const float*)d_in[1];
    const float* xq      = (const float*)d_in[2];
    const int*   xi      = (const int*)  d_in[4];
    const int*   yi      = (const int*)  d_in[5];
    const int*   zi      = (const int*)  d_in[6];
    const float* normals = (const float*)d_in[7];

    int nq = in_sizes[1];
    int nb = in_sizes[4];

    int blocks = (nb + PPB - 1) / PPB;

    if (nq == 200) {
        boundary_loss_fused<200><<<blocks, TPB>>>(outf, q, xq, xi, yi, zi, normals,
                                                  (float*)d_out, nb, nq);
    } else {
        boundary_loss_fused<0><<<blocks, TPB>>>(outf, q, xq, xi, yi, zi, normals,
                                                (float*)d_out, nb, nq);
    }
}